// round 7
// baseline (speedup 1.0000x reference)
#include <cuda_runtime.h>
#include <cuda_bf16.h>

// Inputs (metadata order):
// 0: pred float32 [2M]  1: constr_idx int32 [20M]  2: var_idx int32 [20M]
// 3: coeff float32 [20M]  4: constr_rhs float32 [1M]  5: constr_sense int32 [1M]
// Output: scalar float (mean violation)
//
// Invariant: g_ax is all-zero at entry to every kernel_launch execution.
//  - zero-initialized at module load (first/correctness run)
//  - reduce_kernel re-zeroes each element right after consuming it
// This removes the standalone zeroing pass entirely.

#define MAX_CONSTRS 1000000

__device__ float g_ax[MAX_CONSTRS];   // zero-init by loader; kept zero by reduce

// ---------------------------------------------------------------------------
// scatter: ax[cidx[k]] += coeff[k] * sigmoid(pred[vidx[k]]), 4 nnz/thread.
// LTS-sector-bound (93%); sigmoid MUFU work hides under it (issue=3.5%).
// Thread 0 also zeroes the output scalar (stream-ordered before reduce).
// ---------------------------------------------------------------------------
__device__ __forceinline__ float fast_sigmoid(float x) {
    float t;
    asm("tanh.approx.f32 %0, %1;" : "=f"(t) : "f"(0.5f * x));
    return fmaf(0.5f, t, 0.5f);
}

__global__ void __launch_bounds__(256) scatter_kernel(
        const float*  __restrict__ pred,
        const int4*   __restrict__ cidx4,
        const int4*   __restrict__ vidx4,
        const float4* __restrict__ coeff4,
        float* __restrict__ out,
        int nthreads) {
    int i = blockIdx.x * blockDim.x + threadIdx.x;
    if (i == 0) *out = 0.0f;
    if (i >= nthreads) return;

    int4   c = __ldcs(&cidx4[i]);
    int4   v = __ldcs(&vidx4[i]);
    float4 a = __ldcs(&coeff4[i]);

    // L2-resident random gathers of raw pred
    float p0 = __ldcg(&pred[v.x]);
    float p1 = __ldcg(&pred[v.y]);
    float p2 = __ldcg(&pred[v.z]);
    float p3 = __ldcg(&pred[v.w]);

    // sigmoid on otherwise-idle SM pipes
    float g0 = fast_sigmoid(p0);
    float g1 = fast_sigmoid(p1);
    float g2 = fast_sigmoid(p2);
    float g3 = fast_sigmoid(p3);

    atomicAdd(&g_ax[c.x], a.x * g0);
    atomicAdd(&g_ax[c.y], a.y * g1);
    atomicAdd(&g_ax[c.z], a.z * g2);
    atomicAdd(&g_ax[c.w], a.w * g3);
}

// ---------------------------------------------------------------------------
// reduce: violations + mean, 2x float4 per thread, branchless.
// Re-zeroes each ax element after reading (restores the entry invariant).
// ---------------------------------------------------------------------------
__device__ __forceinline__ float viol(float diff, int sn) {
    float v1 = fmaxf(diff, 0.0f);
    float v2 = fmaxf(-diff, 0.0f);
    float v3 = fabsf(diff);
    return (sn == 1) ? v1 : (sn == 2) ? v2 : (sn == 3) ? v3 : 0.0f;
}

__global__ void reduce_kernel(const float4* __restrict__ rhs4,
                              const int4*   __restrict__ sense4,
                              float* __restrict__ out,
                              int n4, float inv_n) {
    float s = 0.0f;
    float4* ax4 = reinterpret_cast<float4*>(g_ax);
    const float4 z = make_float4(0.f, 0.f, 0.f, 0.f);
    int i = blockIdx.x * blockDim.x * 2 + threadIdx.x;
    int j = i + blockDim.x;
    if (i < n4) {
        float4 ax0 = __ldcg(&ax4[i]);
        float4 rh0 = __ldcs(&rhs4[i]);
        int4   sn0 = __ldcs(&sense4[i]);
        ax4[i] = z;                       // lazy re-zero for next replay
        if (j < n4) {
            float4 ax1 = __ldcg(&ax4[j]);
            float4 rh1 = __ldcs(&rhs4[j]);
            int4   sn1 = __ldcs(&sense4[j]);
            ax4[j] = z;                   // lazy re-zero for next replay
            s += viol(ax1.x - rh1.x, sn1.x);
            s += viol(ax1.y - rh1.y, sn1.y);
            s += viol(ax1.z - rh1.z, sn1.z);
            s += viol(ax1.w - rh1.w, sn1.w);
        }
        s += viol(ax0.x - rh0.x, sn0.x);
        s += viol(ax0.y - rh0.y, sn0.y);
        s += viol(ax0.z - rh0.z, sn0.z);
        s += viol(ax0.w - rh0.w, sn0.w);
    }
    #pragma unroll
    for (int off = 16; off > 0; off >>= 1)
        s += __shfl_down_sync(0xFFFFFFFFu, s, off);

    __shared__ float warp_sums[32];
    int lane = threadIdx.x & 31;
    int wid  = threadIdx.x >> 5;
    if (lane == 0) warp_sums[wid] = s;
    __syncthreads();
    int nwarps = blockDim.x >> 5;
    if (wid == 0) {
        float t = (lane < nwarps) ? warp_sums[lane] : 0.0f;
        #pragma unroll
        for (int off = 16; off > 0; off >>= 1)
            t += __shfl_down_sync(0xFFFFFFFFu, t, off);
        if (lane == 0) atomicAdd(out, t * inv_n);
    }
}

// ---------------------------------------------------------------------------
extern "C" void kernel_launch(void* const* d_in, const int* in_sizes, int n_in,
                              void* d_out, int out_size) {
    const float* pred   = (const float*)d_in[0];
    const int*   cidx   = (const int*)  d_in[1];
    const int*   vidx   = (const int*)  d_in[2];
    const float* coeff  = (const float*)d_in[3];
    const float* rhs    = (const float*)d_in[4];
    const int*   sense  = (const int*)  d_in[5];

    int nnz       = in_sizes[1];
    int n_constrs = in_sizes[4];

    float* out = (float*)d_out;

    // 1) scatter with fused sigmoid (4 nnz/thread); also zeroes *out
    {
        int nthreads = nnz / 4;
        int threads = 256;
        int blocks = (nthreads + threads - 1) / threads;
        scatter_kernel<<<blocks, threads>>>(
            pred,
            reinterpret_cast<const int4*>(cidx),
            reinterpret_cast<const int4*>(vidx),
            reinterpret_cast<const float4*>(coeff),
            out,
            nthreads);
    }

    // 2) violations + mean; re-zeroes ax for the next replay
    {
        int n4 = n_constrs / 4;                 // 250,000
        int threads = 256;
        int blocks = (n4 + threads * 2 - 1) / (threads * 2);   // 489
        reduce_kernel<<<blocks, threads>>>(
            reinterpret_cast<const float4*>(rhs),
            reinterpret_cast<const int4*>(sense),
            out, n4, 1.0f / (float)n_constrs);
    }
}